// round 1
// baseline (speedup 1.0000x reference)
#include <cuda_runtime.h>

#define L_DIM 512
#define B_DIM 64
#define H_DIM 1024

// Scratch (no allocations allowed in kernel_launch)
__device__ __align__(16) float g_u[H_DIM];
__device__ float g_attn[B_DIM * L_DIM];

// ---------------------------------------------------------------------------
// K1: u[h] = sum_k W_att[k, H + h] * v[k]   (only the "We" half of W_att used)
// 32 blocks x 256 threads: each block owns 32 h-values, 8 k-lanes each.
// ---------------------------------------------------------------------------
__global__ void compute_u_kernel(const float* __restrict__ W_att,
                                 const float* __restrict__ vec) {
    __shared__ float red[8][32];
    const int t  = threadIdx.x;       // 0..255
    const int hl = t & 31;            // h within block
    const int kg = t >> 5;            // k-group 0..7
    const int h  = blockIdx.x * 32 + hl;

    float acc = 0.f;
    #pragma unroll 4
    for (int k = kg; k < H_DIM; k += 8) {
        acc += W_att[(size_t)k * (2 * H_DIM) + H_DIM + h] * __ldg(&vec[k]);
    }
    red[kg][hl] = acc;
    __syncthreads();
    if (t < 32) {
        float s = 0.f;
        #pragma unroll
        for (int g = 0; g < 8; g++) s += red[g][t];
        g_u[blockIdx.x * 32 + t] = s;
    }
}

// ---------------------------------------------------------------------------
// K2: attn[b,l] = <hs_encoder[l,b,:], u>   (the 134 MB streaming kernel)
// One warp per (l,b) row. float4 loads, u staged in shared memory.
// ---------------------------------------------------------------------------
__global__ void __launch_bounds__(256) dot_kernel(const float* __restrict__ hs) {
    __shared__ float4 su[H_DIM / 4];          // 4 KB
    const int t = threadIdx.x;
    su[t] = reinterpret_cast<const float4*>(g_u)[t];
    __syncthreads();

    const int warp = t >> 5;
    const int lane = t & 31;
    const int row  = blockIdx.x * 8 + warp;   // 0 .. L*B-1, row = l*B + b

    const float4* rp = reinterpret_cast<const float4*>(hs) + (size_t)row * (H_DIM / 4);

    float acc = 0.f;
    #pragma unroll
    for (int j = 0; j < 8; j++) {
        const int idx = lane + j * 32;
        const float4 x = rp[idx];
        const float4 u = su[idx];
        acc += x.x * u.x + x.y * u.y + x.z * u.z + x.w * u.w;
    }
    #pragma unroll
    for (int o = 16; o; o >>= 1)
        acc += __shfl_xor_sync(0xffffffffu, acc, o);

    if (lane == 0) {
        const int l = row >> 6;               // row / B
        const int b = row & 63;               // row % B
        g_attn[b * L_DIM + l] = acc;
    }
}

// ---------------------------------------------------------------------------
// K3: out[b, 0, l] = softmax_l(attn[b, l]).  One block per batch, 512 threads.
// ---------------------------------------------------------------------------
__global__ void __launch_bounds__(512) softmax_kernel(float* __restrict__ out) {
    __shared__ float sm[16];
    const int b = blockIdx.x;
    const int t = threadIdx.x;                // 0..511
    const int lane = t & 31, w = t >> 5;

    const float a = g_attn[b * L_DIM + t];

    // block max
    float m = a;
    #pragma unroll
    for (int o = 16; o; o >>= 1) m = fmaxf(m, __shfl_xor_sync(0xffffffffu, m, o));
    if (lane == 0) sm[w] = m;
    __syncthreads();
    float M = sm[0];
    #pragma unroll
    for (int i = 1; i < 16; i++) M = fmaxf(M, sm[i]);
    __syncthreads();

    const float e = expf(a - M);

    // block sum
    float s = e;
    #pragma unroll
    for (int o = 16; o; o >>= 1) s += __shfl_xor_sync(0xffffffffu, s, o);
    if (lane == 0) sm[w] = s;
    __syncthreads();
    float S = sm[0];
    #pragma unroll
    for (int i = 1; i < 16; i++) S += sm[i];

    out[b * L_DIM + t] = e / S;
}

// ---------------------------------------------------------------------------
// Inputs (metadata order): hidden, hs_encoder, W_att, b_att, vector
// hidden / b_att / Wh are mathematically dead (softmax shift invariance).
// ---------------------------------------------------------------------------
extern "C" void kernel_launch(void* const* d_in, const int* in_sizes, int n_in,
                              void* d_out, int out_size) {
    const float* hs  = (const float*)d_in[1];   // (512, 64, 1024)
    const float* W   = (const float*)d_in[2];   // (1024, 2048)
    const float* vec = (const float*)d_in[4];   // (1024, 1)
    float* out = (float*)d_out;                 // (64, 1, 512)

    compute_u_kernel<<<H_DIM / 32, 256>>>(W, vec);
    dot_kernel<<<(L_DIM * B_DIM) / 8, 256>>>(hs);
    softmax_kernel<<<B_DIM, 512>>>(out);
}

// round 3
// speedup vs baseline: 1.2836x; 1.2836x over previous
#include <cuda_runtime.h>

#define L_DIM 512
#define B_DIM 64
#define H_DIM 1024

// Scratch (no allocations allowed)
__device__ __align__(16) float g_u[H_DIM];
__device__ float g_attn[B_DIM * L_DIM];

// ---------------------------------------------------------------------------
// K1: u[h] = sum_k W_att[k, H + h] * v[k]
// 128 blocks x 256 threads. Block b owns k-rows [8b, 8b+8).
// Thread t owns h-columns [4t, 4t+4) -> each row is one coalesced 4KB sweep.
// Register accumulation across 8 rows, then 4 atomicAdds (g_u pre-zeroed).
// ---------------------------------------------------------------------------
#define K1_ROWS 8
__global__ void __launch_bounds__(256) compute_u_kernel(const float* __restrict__ W_att,
                                                        const float* __restrict__ vec) {
    const int t  = threadIdx.x;            // 0..255
    const int k0 = blockIdx.x * K1_ROWS;

    float ax = 0.f, ay = 0.f, az = 0.f, aw = 0.f;
    #pragma unroll
    for (int r = 0; r < K1_ROWS; r++) {
        const int k = k0 + r;
        const float vk = __ldg(&vec[k]);
        const float4 w = *reinterpret_cast<const float4*>(
            &W_att[(size_t)k * (2 * H_DIM) + H_DIM + t * 4]);
        ax += w.x * vk;
        ay += w.y * vk;
        az += w.z * vk;
        aw += w.w * vk;
    }
    atomicAdd(&g_u[t * 4 + 0], ax);
    atomicAdd(&g_u[t * 4 + 1], ay);
    atomicAdd(&g_u[t * 4 + 2], az);
    atomicAdd(&g_u[t * 4 + 3], aw);
}

// ---------------------------------------------------------------------------
// K2: attn[b,l] = <hs_encoder[l,b,:], u>   (the 134 MB streaming kernel)
// One warp per (l,b) row. float4 loads, u staged in shared memory.
// ---------------------------------------------------------------------------
__global__ void __launch_bounds__(256) dot_kernel(const float* __restrict__ hs) {
    __shared__ float4 su[H_DIM / 4];          // 4 KB
    const int t = threadIdx.x;
    su[t] = reinterpret_cast<const float4*>(g_u)[t];
    __syncthreads();

    const int warp = t >> 5;
    const int lane = t & 31;
    const int row  = blockIdx.x * 8 + warp;   // row = l*B + b

    const float4* rp = reinterpret_cast<const float4*>(hs) + (size_t)row * (H_DIM / 4);

    float acc = 0.f;
    #pragma unroll
    for (int j = 0; j < 8; j++) {
        const int idx = lane + j * 32;
        const float4 x = rp[idx];
        const float4 u = su[idx];
        acc += x.x * u.x + x.y * u.y + x.z * u.z + x.w * u.w;
    }
    #pragma unroll
    for (int o = 16; o; o >>= 1)
        acc += __shfl_xor_sync(0xffffffffu, acc, o);

    if (lane == 0) {
        const int l = row >> 6;               // row / B
        const int b = row & 63;               // row % B
        g_attn[b * L_DIM + l] = acc;
    }
}

// ---------------------------------------------------------------------------
// K3: out[b, 0, l] = softmax_l(attn[b, l]).  One block per batch, 512 threads.
// ---------------------------------------------------------------------------
__global__ void __launch_bounds__(512) softmax_kernel(float* __restrict__ out) {
    __shared__ float sm[16];
    const int b = blockIdx.x;
    const int t = threadIdx.x;                // 0..511
    const int lane = t & 31, w = t >> 5;

    const float a = g_attn[b * L_DIM + t];

    float m = a;
    #pragma unroll
    for (int o = 16; o; o >>= 1) m = fmaxf(m, __shfl_xor_sync(0xffffffffu, m, o));
    if (lane == 0) sm[w] = m;
    __syncthreads();
    float M = sm[0];
    #pragma unroll
    for (int i = 1; i < 16; i++) M = fmaxf(M, sm[i]);
    __syncthreads();

    const float e = expf(a - M);

    float s = e;
    #pragma unroll
    for (int o = 16; o; o >>= 1) s += __shfl_xor_sync(0xffffffffu, s, o);
    if (lane == 0) sm[w] = s;
    __syncthreads();
    float S = sm[0];
    #pragma unroll
    for (int i = 1; i < 16; i++) S += sm[i];

    out[b * L_DIM + t] = e / S;
}

// ---------------------------------------------------------------------------
// Inputs (metadata order): hidden, hs_encoder, W_att, b_att, vector
// hidden / b_att / Wh are mathematically dead (softmax shift invariance).
// ---------------------------------------------------------------------------
extern "C" void kernel_launch(void* const* d_in, const int* in_sizes, int n_in,
                              void* d_out, int out_size) {
    const float* hs  = (const float*)d_in[1];   // (512, 64, 1024)
    const float* W   = (const float*)d_in[2];   // (1024, 2048)
    const float* vec = (const float*)d_in[4];   // (1024, 1)
    float* out = (float*)d_out;                 // (64, 1, 512)

    static void* u_ptr = nullptr;
    if (!u_ptr) cudaGetSymbolAddress(&u_ptr, g_u);
    cudaMemsetAsync(u_ptr, 0, H_DIM * sizeof(float));

    compute_u_kernel<<<H_DIM / K1_ROWS, 256>>>(W, vec);
    dot_kernel<<<(L_DIM * B_DIM) / 8, 256>>>(hs);
    softmax_kernel<<<B_DIM, 512>>>(out);
}